// round 1
// baseline (speedup 1.0000x reference)
#include <cuda_runtime.h>
#include <cstdint>

// CRF log-likelihood: B=256 sequences, M=1024 steps, D=128 feat, N=26 labels.
// Pipeline:
//   1) emis_kernel : e[b,m,a] = X[b,m,:] . W[a,:]          (f32x2 FFMA GEMM)
//   2) scan_kernel : per-sequence forward algorithm in scaled-prob space
//   3) reduce_kernel: mean over 256 per-sequence log-probs -> d_out[0]

#define B_ 256
#define M_ 1024
#define D_ 128
#define N_ 26

// Scratch (device globals: allocation-free per harness rules)
__device__ float g_e[(size_t)B_ * M_ * N_];   // 27.3 MB emissions
__device__ float g_res[B_];                   // per-sequence log-probs

// ---------------------------------------------------------------------------
// packed f32x2 FMA (sm_103a FFMA2) — only reachable via PTX
// ---------------------------------------------------------------------------
__device__ __forceinline__ unsigned long long fma2(unsigned long long a,
                                                   unsigned long long b,
                                                   unsigned long long c) {
    unsigned long long d;
    asm("fma.rn.f32x2 %0, %1, %2, %3;" : "=l"(d) : "l"(a), "l"(b), "l"(c));
    return d;
}

// ---------------------------------------------------------------------------
// Kernel 1: emissions e = X @ W^T
//   block = 256 threads (8 warps), block tile = 256 rows, warp tile = 32 rows.
//   Per warp: stage 8 rows of X into smem (coalesced), then d-loop with
//   8-row register accumulators; W column (lane = label) read via conflict-free
//   LDS.128 from padded smem; FMA done as f32x2 over adjacent dims.
// ---------------------------------------------------------------------------
__global__ __launch_bounds__(256) void emis_kernel(const float* __restrict__ X,
                                                   const float* __restrict__ W) {
    __shared__ float Ws[26][132];       // pad 132 -> conflict-free float4 reads
    __shared__ float xs[8][8][128];     // [warp][row][dim]

    const int tid = threadIdx.x;
    for (int i = tid; i < 26 * 128; i += 256) Ws[i >> 7][i & 127] = W[i];
    __syncthreads();

    const int w    = tid >> 5;
    const int lane = tid & 31;
    const int a    = lane < 26 ? lane : 25;   // clamp; lanes 26-31 compute junk, never store
    const ulonglong2* wrow = (const ulonglong2*)&Ws[a][0];

    for (int chunk = 0; chunk < 4; chunk++) {
        const int rowbase = blockIdx.x * 256 + w * 32 + chunk * 8;

        // stage 8 rows (1024 floats) coalesced
        const float4* xsrc = (const float4*)(X + (size_t)rowbase * D_);
        float4* xdst = (float4*)&xs[w][0][0];
#pragma unroll
        for (int i = 0; i < 8; i++) xdst[i * 32 + lane] = xsrc[i * 32 + lane];
        __syncwarp();

        unsigned long long acc[8][2];
#pragma unroll
        for (int r = 0; r < 8; r++) { acc[r][0] = 0ull; acc[r][1] = 0ull; }

#pragma unroll
        for (int d4 = 0; d4 < 32; d4++) {
            const ulonglong2 w2 = wrow[d4];              // W[a][4d4..4d4+3]
#pragma unroll
            for (int r = 0; r < 8; r++) {
                const ulonglong2 x2 = *(const ulonglong2*)&xs[w][r][d4 * 4];
                acc[r][0] = fma2(x2.x, w2.x, acc[r][0]);
                acc[r][1] = fma2(x2.y, w2.y, acc[r][1]);
            }
        }

#pragma unroll
        for (int r = 0; r < 8; r++) {
            float lo0 = __int_as_float((int)(acc[r][0] & 0xffffffffull));
            float hi0 = __int_as_float((int)(acc[r][0] >> 32));
            float lo1 = __int_as_float((int)(acc[r][1] & 0xffffffffull));
            float hi1 = __int_as_float((int)(acc[r][1] >> 32));
            float s = (lo0 + hi0) + (lo1 + hi1);
            if (lane < 26) g_e[(size_t)(rowbase + r) * N_ + lane] = s;
        }
        __syncwarp();   // before restaging xs next chunk
    }
}

// ---------------------------------------------------------------------------
// Kernel 2: forward scan, one warp per sequence, lane = label.
//   Scaled-prob recurrence: v_new[a] = E[a] * sum_b v[b]*ET[b,a]
//   (E = exp(e), ET = exp(T) — both off the critical path).
//   Normalize every 8 steps: C += log(v0), v /= v0.
//   logZ = C + log(sum v_last).  Also accumulates the unnormalized score.
// ---------------------------------------------------------------------------
__global__ __launch_bounds__(32) void scan_kernel(const int* __restrict__ labels,
                                                  const float* __restrict__ Tg) {
    const int seq  = blockIdx.x;
    const int lane = threadIdx.x;
    const bool active = lane < N_;

    float ETc[26];   // column `lane` of exp(T): ETc[b] = exp(T[b][lane])
#pragma unroll
    for (int b = 0; b < 26; b++)
        ETc[b] = active ? __expf(__ldg(Tg + b * 26 + lane)) : 0.f;

    const float* er = g_e + (size_t)seq * M_ * N_;
    const int*  lab = labels + seq * M_;

    int   y_prev = __ldg(lab);
    float e0     = active ? __ldg(er + lane) : 0.f;
    float v      = active ? __expf(e0) : 0.f;     // lf[0] = e[0]
    float C      = 0.f;
    float sum_e  = (lane == y_prev) ? e0 : 0.f;
    float sum_t  = 0.f;

    // prefetch ring, distance 8
    float ebuf[8], Ebuf[8]; int lbuf[8];
#pragma unroll
    for (int i = 0; i < 8; i++) {
        ebuf[i] = active ? __ldg(er + (size_t)(1 + i) * 26 + lane) : 0.f;
        lbuf[i] = __ldg(lab + 1 + i);
    }
#pragma unroll
    for (int i = 0; i < 8; i++) Ebuf[i] = __expf(ebuf[i]);

    int m = 1;
    for (int blk = 0; blk < 127; blk++) {       // steps m = 1 .. 1016
#pragma unroll
        for (int j = 0; j < 8; j++) {
            const int y = lbuf[j];
            sum_t += __ldg(Tg + y_prev * 26 + y);
            y_prev = y;
            sum_e += (lane == y) ? ebuf[j] : 0.f;

            float acc[4] = {0.f, 0.f, 0.f, 0.f};
#pragma unroll
            for (int b = 0; b < 26; b++) {
                float vb = __shfl_sync(0xffffffffu, v, b);
                acc[b & 3] += vb * ETc[b];
            }
            float s = (acc[0] + acc[1]) + (acc[2] + acc[3]);
            v = Ebuf[j] * s;

            const int mn = m + 8;
            if (mn <= 1023) {                   // refill ring
                ebuf[j] = active ? __ldg(er + (size_t)mn * 26 + lane) : 0.f;
                lbuf[j] = __ldg(lab + mn);
                Ebuf[j] = __expf(ebuf[j]);
            }
            m++;
        }
        // periodic renormalization (pivot = lane 0; spread bound keeps v0 safe)
        float v0 = __shfl_sync(0xffffffffu, v, 0);
        C += __logf(v0);
        v *= __fdividef(1.f, v0);
    }

    // tail: m = 1017 .. 1023 (slots 0..6), no refill, no renorm needed
#pragma unroll
    for (int j = 0; j < 7; j++) {
        const int y = lbuf[j];
        sum_t += __ldg(Tg + y_prev * 26 + y);
        y_prev = y;
        sum_e += (lane == y) ? ebuf[j] : 0.f;

        float acc[4] = {0.f, 0.f, 0.f, 0.f};
#pragma unroll
        for (int b = 0; b < 26; b++) {
            float vb = __shfl_sync(0xffffffffu, v, b);
            acc[b & 3] += vb * ETc[b];
        }
        float s = (acc[0] + acc[1]) + (acc[2] + acc[3]);
        v = Ebuf[j] * s;
    }

    // logZ = C + log(sum_a v[a]); unnorm = sum_e + sum_t
    float sv = v;
#pragma unroll
    for (int off = 16; off; off >>= 1) sv += __shfl_xor_sync(0xffffffffu, sv, off);
    float logZ = C + __logf(sv);

    float se = sum_e;
#pragma unroll
    for (int off = 16; off; off >>= 1) se += __shfl_xor_sync(0xffffffffu, se, off);

    if (lane == 0) g_res[seq] = (se + sum_t) - logZ;
}

// ---------------------------------------------------------------------------
// Kernel 3: mean over 256 sequences -> d_out[0]
// ---------------------------------------------------------------------------
__global__ __launch_bounds__(256) void reduce_kernel(float* __restrict__ out) {
    const int tid = threadIdx.x;
    float val = g_res[tid];
#pragma unroll
    for (int off = 16; off; off >>= 1) val += __shfl_xor_sync(0xffffffffu, val, off);

    __shared__ float sh[8];
    if ((tid & 31) == 0) sh[tid >> 5] = val;
    __syncthreads();
    if (tid < 8) {
        float t = sh[tid];
#pragma unroll
        for (int off = 4; off; off >>= 1) t += __shfl_xor_sync(0xffu, t, off);
        if (tid == 0) out[0] = t * (1.0f / 256.0f);
    }
}

// ---------------------------------------------------------------------------
extern "C" void kernel_launch(void* const* d_in, const int* in_sizes, int n_in,
                              void* d_out, int out_size) {
    const float* X      = (const float*)d_in[0];   // [256,1024,128] f32
    const int*   labels = (const int*)d_in[1];     // [256,1024] i32
    const float* W      = (const float*)d_in[2];   // [26,128] f32
    const float* Tm     = (const float*)d_in[3];   // [26,26] f32

    emis_kernel<<<1024, 256>>>(X, W);
    scan_kernel<<<B_, 32>>>(labels, Tm);
    reduce_kernel<<<1, 256>>>((float*)d_out);
}

// round 2
// speedup vs baseline: 1.5900x; 1.5900x over previous
#include <cuda_runtime.h>
#include <cstdint>

// CRF log-likelihood: B=256 sequences, M=1024 steps, D=128 feat, N=26 labels.
//   1) emis_kernel : e[b,m,a] = X[b,m,:] . W[a,:]          (f32x2 FFMA GEMM)
//   2) scan_kernel : per-sequence forward algorithm in scaled-prob space
//   3) reduce_kernel: mean over 256 per-sequence log-probs -> d_out[0]

#define B_ 256
#define M_ 1024
#define D_ 128
#define N_ 26

__device__ float g_e[(size_t)B_ * M_ * N_];   // 27.3 MB emissions (stays in L2)
__device__ float g_res[B_];                   // per-sequence log-probs

// packed f32x2 FMA (sm_103a FFMA2)
__device__ __forceinline__ unsigned long long fma2(unsigned long long a,
                                                   unsigned long long b,
                                                   unsigned long long c) {
    unsigned long long d;
    asm("fma.rn.f32x2 %0, %1, %2, %3;" : "=l"(d) : "l"(a), "l"(b), "l"(c));
    return d;
}

// ---------------------------------------------------------------------------
// Kernel 1: emissions e = X @ W^T  (unchanged from R1 — 94us, revisit next)
// ---------------------------------------------------------------------------
__global__ __launch_bounds__(256) void emis_kernel(const float* __restrict__ X,
                                                   const float* __restrict__ W) {
    __shared__ float Ws[26][132];
    __shared__ float xs[8][8][128];

    const int tid = threadIdx.x;
    for (int i = tid; i < 26 * 128; i += 256) Ws[i >> 7][i & 127] = W[i];
    __syncthreads();

    const int w    = tid >> 5;
    const int lane = tid & 31;
    const int a    = lane < 26 ? lane : 25;
    const ulonglong2* wrow = (const ulonglong2*)&Ws[a][0];

    for (int chunk = 0; chunk < 4; chunk++) {
        const int rowbase = blockIdx.x * 256 + w * 32 + chunk * 8;

        const float4* xsrc = (const float4*)(X + (size_t)rowbase * D_);
        float4* xdst = (float4*)&xs[w][0][0];
#pragma unroll
        for (int i = 0; i < 8; i++) xdst[i * 32 + lane] = xsrc[i * 32 + lane];
        __syncwarp();

        unsigned long long acc[8][2];
#pragma unroll
        for (int r = 0; r < 8; r++) { acc[r][0] = 0ull; acc[r][1] = 0ull; }

#pragma unroll
        for (int d4 = 0; d4 < 32; d4++) {
            const ulonglong2 w2 = wrow[d4];
#pragma unroll
            for (int r = 0; r < 8; r++) {
                const ulonglong2 x2 = *(const ulonglong2*)&xs[w][r][d4 * 4];
                acc[r][0] = fma2(x2.x, w2.x, acc[r][0]);
                acc[r][1] = fma2(x2.y, w2.y, acc[r][1]);
            }
        }

#pragma unroll
        for (int r = 0; r < 8; r++) {
            float lo0 = __int_as_float((int)(acc[r][0] & 0xffffffffull));
            float hi0 = __int_as_float((int)(acc[r][0] >> 32));
            float lo1 = __int_as_float((int)(acc[r][1] & 0xffffffffull));
            float hi1 = __int_as_float((int)(acc[r][1] >> 32));
            float s = (lo0 + hi0) + (lo1 + hi1);
            if (lane < 26) g_e[(size_t)(rowbase + r) * N_ + lane] = s;
        }
        __syncwarp();
    }
}

// ---------------------------------------------------------------------------
// Kernel 2: forward scan, one warp per sequence, lane = label.
//   v_new[a] = Ecur[a] * sum_b v[b]*ET[b,a],  Ecur = exp(e) computed one
//   iteration ahead of use; raw e / labels / T-values prefetched 8 steps
//   ahead in rings so no load latency is exposed in the step body.
//   Renormalize every 8 steps by exact power-of-2 (exponent bit surgery).
// ---------------------------------------------------------------------------
__global__ __launch_bounds__(32) void scan_kernel(const int* __restrict__ labels,
                                                  const float* __restrict__ Tg) {
    const int seq  = blockIdx.x;
    const int lane = threadIdx.x;
    const bool active = lane < N_;

    float ETc[26];   // ETc[b] = exp(T[b][lane])  (column of exp(T); 0 on idle lanes)
#pragma unroll
    for (int b = 0; b < 26; b++)
        ETc[b] = active ? __expf(__ldg(Tg + b * 26 + lane)) : 0.f;

    const float* er = g_e + (size_t)seq * M_ * N_;
    const int*  lab = labels + seq * M_;

    const int y0 = __ldg(lab);
    float e0     = active ? __ldg(er + lane) : 0.f;
    float v      = active ? __expf(e0) : 0.f;     // lf[0] = e[0]
    float Cl2    = 0.f;                            // accumulated log2 scale
    float sum_e  = (lane == y0) ? e0 : 0.f;
    float sum_t  = 0.f;

    // prefetch rings, distance 8: raw emission, label, transition score
    float ebuf[8], tbuf[8]; int lbuf[8];
    {
        int y_pf_prev = y0;
#pragma unroll
        for (int i = 0; i < 8; i++) {
            ebuf[i] = active ? __ldg(er + (size_t)(1 + i) * 26 + lane) : 0.f;
            int y   = __ldg(lab + 1 + i);
            tbuf[i] = __ldg(Tg + y_pf_prev * 26 + y);
            lbuf[i] = y;
            y_pf_prev = y;
        }
        // continue the prefetch chain state for loop refills
        // (store in a register that survives: y_pf_prev re-declared below)
        // -- handled by hoisting y_pf_prev outside this scope:
    }
    int y_pf_prev = lbuf[7];

    float Ecur = __expf(ebuf[0]);   // exp for step 1, ready before loop

    int m = 1;
    for (int blk = 0; blk < 127; blk++) {       // steps m = 1 .. 1016
#pragma unroll
        for (int j = 0; j < 8; j++) {
            // stage the NEXT step's exp early (its ebuf slot is not yet refilled)
            float Enext = __expf(ebuf[(j + 1) & 7]);

            // bookkeeping off the critical path (all ring-resident)
            sum_t += tbuf[j];
            sum_e += (lane == lbuf[j]) ? ebuf[j] : 0.f;

            // 26-wide matvec via shfl broadcast
            float acc[4] = {0.f, 0.f, 0.f, 0.f};
#pragma unroll
            for (int b = 0; b < 26; b++) {
                float vb = __shfl_sync(0xffffffffu, v, b);
                acc[b & 3] += vb * ETc[b];
            }
            float s = (acc[0] + acc[1]) + (acc[2] + acc[3]);
            v = Ecur * s;
            Ecur = Enext;

            // refill ring slot j for step m+8 (consumed 8 steps from now)
            const int mn = m + 8;
            if (mn <= 1023) {
                ebuf[j] = active ? __ldg(er + (size_t)mn * 26 + lane) : 0.f;
                int yn  = __ldg(lab + mn);
                tbuf[j] = __ldg(Tg + y_pf_prev * 26 + yn);
                lbuf[j] = yn;
                y_pf_prev = yn;
            }
            m++;
        }
        // exact power-of-2 renorm: v *= 2^-ex, Cl2 += ex  (no MUFU, no div)
        float v0 = __shfl_sync(0xffffffffu, v, 0);
        int ex = (__float_as_int(v0) >> 23) - 127;
        Cl2 += (float)ex;
        if (active) v = __int_as_float(__float_as_int(v) - (ex << 23));
    }

    // tail: steps 1017..1023 (slots 0..6), no refill, no renorm
#pragma unroll
    for (int j = 0; j < 7; j++) {
        float Enext = (j < 6) ? __expf(ebuf[j + 1]) : 1.f;
        sum_t += tbuf[j];
        sum_e += (lane == lbuf[j]) ? ebuf[j] : 0.f;

        float acc[4] = {0.f, 0.f, 0.f, 0.f};
#pragma unroll
        for (int b = 0; b < 26; b++) {
            float vb = __shfl_sync(0xffffffffu, v, b);
            acc[b & 3] += vb * ETc[b];
        }
        float s = (acc[0] + acc[1]) + (acc[2] + acc[3]);
        v = Ecur * s;
        Ecur = Enext;
    }

    // logZ = Cl2*ln2 + log(sum_a v[a]);  unnorm = sum_e + sum_t
    float sv = v;
#pragma unroll
    for (int off = 16; off; off >>= 1) sv += __shfl_xor_sync(0xffffffffu, sv, off);
    const float LN2 = 0.6931471805599453f;
    float logZ = Cl2 * LN2 + __logf(sv);

    float se = sum_e;
#pragma unroll
    for (int off = 16; off; off >>= 1) se += __shfl_xor_sync(0xffffffffu, se, off);

    if (lane == 0) g_res[seq] = (se + sum_t) - logZ;
}

// ---------------------------------------------------------------------------
// Kernel 3: mean over 256 sequences -> d_out[0]
// ---------------------------------------------------------------------------
__global__ __launch_bounds__(256) void reduce_kernel(float* __restrict__ out) {
    const int tid = threadIdx.x;
    float val = g_res[tid];
#pragma unroll
    for (int off = 16; off; off >>= 1) val += __shfl_xor_sync(0xffffffffu, val, off);

    __shared__ float sh[8];
    if ((tid & 31) == 0) sh[tid >> 5] = val;
    __syncthreads();
    if (tid < 8) {
        float t = sh[tid];
#pragma unroll
        for (int off = 4; off; off >>= 1) t += __shfl_xor_sync(0xffu, t, off);
        if (tid == 0) out[0] = t * (1.0f / 256.0f);
    }
}

// ---------------------------------------------------------------------------
extern "C" void kernel_launch(void* const* d_in, const int* in_sizes, int n_in,
                              void* d_out, int out_size) {
    const float* X      = (const float*)d_in[0];   // [256,1024,128] f32
    const int*   labels = (const int*)d_in[1];     // [256,1024] i32
    const float* W      = (const float*)d_in[2];   // [26,128] f32
    const float* Tm     = (const float*)d_in[3];   // [26,26] f32

    emis_kernel<<<1024, 256>>>(X, W);
    scan_kernel<<<B_, 32>>>(labels, Tm);
    reduce_kernel<<<1, 256>>>((float*)d_out);
}

// round 3
// speedup vs baseline: 2.2892x; 1.4397x over previous
#include <cuda_runtime.h>
#include <cstdint>

// CRF log-likelihood: B=256, M=1024, D=128, N=26.
//   1) emis_kernel     : e = X @ W^T                       (f32x2 FFMA GEMM)
//   2) scan_kernel     : grid 512 — forward half (v) AND backward/adjoint
//                        half (u) per sequence, meeting at m=511.
//   3) score_combine   : unnormalized score (parallel over m) + dot(v,u)
//   4) reduce_kernel   : mean -> d_out[0]

#define B_ 256
#define M_ 1024
#define D_ 128
#define N_ 26
#define FULLM 0xffffffffu

__device__ float g_e[(size_t)B_ * M_ * N_];   // 27.3 MB emissions
__device__ float g_midv[B_ * 32];             // forward state at m=511
__device__ float g_midu[B_ * 32];             // adjoint state at m=511
__device__ float g_cfw[B_];                   // forward log2-scale
__device__ float g_cbw[B_];                   // backward log2-scale
__device__ float g_res[B_];                   // per-sequence log-probs

__device__ __forceinline__ unsigned long long fma2(unsigned long long a,
                                                   unsigned long long b,
                                                   unsigned long long c) {
    unsigned long long d;
    asm("fma.rn.f32x2 %0, %1, %2, %3;" : "=l"(d) : "l"(a), "l"(b), "l"(c));
    return d;
}

// ---------------------------------------------------------------------------
// Kernel 1: emissions e = X @ W^T  (unchanged; 94us; MMA rewrite next round)
// ---------------------------------------------------------------------------
__global__ __launch_bounds__(256) void emis_kernel(const float* __restrict__ X,
                                                   const float* __restrict__ W) {
    __shared__ float Ws[26][132];
    __shared__ float xs[8][8][128];

    const int tid = threadIdx.x;
    for (int i = tid; i < 26 * 128; i += 256) Ws[i >> 7][i & 127] = W[i];
    __syncthreads();

    const int w    = tid >> 5;
    const int lane = tid & 31;
    const int a    = lane < 26 ? lane : 25;
    const ulonglong2* wrow = (const ulonglong2*)&Ws[a][0];

    for (int chunk = 0; chunk < 4; chunk++) {
        const int rowbase = blockIdx.x * 256 + w * 32 + chunk * 8;

        const float4* xsrc = (const float4*)(X + (size_t)rowbase * D_);
        float4* xdst = (float4*)&xs[w][0][0];
#pragma unroll
        for (int i = 0; i < 8; i++) xdst[i * 32 + lane] = xsrc[i * 32 + lane];
        __syncwarp();

        unsigned long long acc[8][2];
#pragma unroll
        for (int r = 0; r < 8; r++) { acc[r][0] = 0ull; acc[r][1] = 0ull; }

#pragma unroll
        for (int d4 = 0; d4 < 32; d4++) {
            const ulonglong2 w2 = wrow[d4];
#pragma unroll
            for (int r = 0; r < 8; r++) {
                const ulonglong2 x2 = *(const ulonglong2*)&xs[w][r][d4 * 4];
                acc[r][0] = fma2(x2.x, w2.x, acc[r][0]);
                acc[r][1] = fma2(x2.y, w2.y, acc[r][1]);
            }
        }

#pragma unroll
        for (int r = 0; r < 8; r++) {
            float lo0 = __int_as_float((int)(acc[r][0] & 0xffffffffull));
            float hi0 = __int_as_float((int)(acc[r][0] >> 32));
            float lo1 = __int_as_float((int)(acc[r][1] & 0xffffffffull));
            float hi1 = __int_as_float((int)(acc[r][1] >> 32));
            float s = (lo0 + hi0) + (lo1 + hi1);
            if (lane < 26) g_e[(size_t)(rowbase + r) * N_ + lane] = s;
        }
        __syncwarp();
    }
}

// ---------------------------------------------------------------------------
// Kernel 2: split scan. blockIdx even -> forward, odd -> backward (adjoint).
//   forward : v_m[a] = E_m[a] * sum_b exp(T[b,a]) v_{m-1}[b],   m = 1..511
//   backward: u_{m-1}[b] = sum_a exp(T[b,a]) E_m[a] u_m[a],     m = 1023..512
//   Minimal state; all 26 shfls batched; exp one step ahead; renorm every 8
//   steps via exact exponent-field subtraction (no MUFU/div).
// ---------------------------------------------------------------------------
__global__ __launch_bounds__(32) void scan_kernel(const float* __restrict__ Tg) {
    const int seq  = blockIdx.x >> 1;
    const int bwd  = blockIdx.x & 1;
    const int lane = threadIdx.x;
    const bool act = lane < N_;
    const float* er = g_e + (size_t)seq * M_ * N_;

    float Cl2 = 0.f;

    if (!bwd) {
        // ---------------- forward: lane = destination label a ----------------
        float ETc[26];                              // ETc[b] = exp(T[b][lane])
#pragma unroll
        for (int b = 0; b < 26; b++)
            ETc[b] = act ? __expf(__ldg(Tg + b * 26 + lane)) : 0.f;

        float v = act ? __expf(__ldg(er + lane)) : 0.f;   // v_0 = exp(e_0)

        float ebuf[8];
#pragma unroll
        for (int i = 0; i < 8; i++)
            ebuf[i] = act ? __ldg(er + (size_t)(1 + i) * 26 + lane) : 0.f;
        float Ecur = __expf(ebuf[0]);

        int m = 1;
        for (int blk = 0; blk < 63; blk++) {        // m = 1..504
#pragma unroll
            for (int j = 0; j < 8; j++) {
                float Enext = __expf(ebuf[(j + 1) & 7]);
                float t[26];
#pragma unroll
                for (int b = 0; b < 26; b++) t[b] = __shfl_sync(FULLM, v, b);
                float a0 = 0.f, a1 = 0.f, a2 = 0.f, a3 = 0.f;
#pragma unroll
                for (int b = 0; b < 26; b += 4) {
                    a0 += t[b] * ETc[b];
                    a1 += t[b + 1] * ETc[b + 1];
                    if (b + 2 < 26) a2 += t[b + 2] * ETc[b + 2];
                    if (b + 3 < 26) a3 += t[b + 3] * ETc[b + 3];
                }
                v = Ecur * ((a0 + a1) + (a2 + a3));
                Ecur = Enext;

                const int mn = m + 8;
                if (mn <= 511)
                    ebuf[j] = act ? __ldg(er + (size_t)mn * 26 + lane) : 0.f;
                m++;
            }
            float v0 = __shfl_sync(FULLM, v, 0);
            int ex = (__float_as_int(v0) >> 23) - 127;
            Cl2 += (float)ex;
            if (act) v = __int_as_float(__float_as_int(v) - (ex << 23));
        }
        // tail m = 505..511 (slots 0..6)
#pragma unroll
        for (int j = 0; j < 7; j++) {
            float Enext = (j < 6) ? __expf(ebuf[j + 1]) : 1.f;
            float t[26];
#pragma unroll
            for (int b = 0; b < 26; b++) t[b] = __shfl_sync(FULLM, v, b);
            float a0 = 0.f, a1 = 0.f, a2 = 0.f, a3 = 0.f;
#pragma unroll
            for (int b = 0; b < 26; b += 4) {
                a0 += t[b] * ETc[b];
                a1 += t[b + 1] * ETc[b + 1];
                if (b + 2 < 26) a2 += t[b + 2] * ETc[b + 2];
                if (b + 3 < 26) a3 += t[b + 3] * ETc[b + 3];
            }
            v = Ecur * ((a0 + a1) + (a2 + a3));
            Ecur = Enext;
        }
        if (act) g_midv[seq * 32 + lane] = v;
        if (lane == 0) g_cfw[seq] = Cl2;
    } else {
        // ------------- backward adjoint: lane = source label b ---------------
        float ETr[26];                              // ETr[a] = exp(T[lane][a])
#pragma unroll
        for (int a = 0; a < 26; a++)
            ETr[a] = act ? __expf(__ldg(Tg + lane * 26 + a)) : 0.f;

        float u = act ? 1.f : 0.f;                  // u_1023 = 1

        float ebuf[8];
#pragma unroll
        for (int i = 0; i < 8; i++)
            ebuf[i] = act ? __ldg(er + (size_t)(1023 - i) * 26 + lane) : 0.f;
        float Ecur = __expf(ebuf[0]);               // E_1023

        int k = 0;
        for (int blk = 0; blk < 64; blk++) {        // k = 0..511, m = 1023-k
#pragma unroll
            for (int j = 0; j < 8; j++) {
                float Enext = __expf(ebuf[(j + 1) & 7]);
                float w = Ecur * u;                 // lane a supplies E_m[a]*u[a]
                float t[26];
#pragma unroll
                for (int a = 0; a < 26; a++) t[a] = __shfl_sync(FULLM, w, a);
                float a0 = 0.f, a1 = 0.f, a2 = 0.f, a3 = 0.f;
#pragma unroll
                for (int a = 0; a < 26; a += 4) {
                    a0 += t[a] * ETr[a];
                    a1 += t[a + 1] * ETr[a + 1];
                    if (a + 2 < 26) a2 += t[a + 2] * ETr[a + 2];
                    if (a + 3 < 26) a3 += t[a + 3] * ETr[a + 3];
                }
                u = (a0 + a1) + (a2 + a3);
                Ecur = Enext;

                const int kn = k + 8;               // refill for step k+8
                if (kn <= 511)
                    ebuf[j] = act ? __ldg(er + (size_t)(1023 - kn) * 26 + lane) : 0.f;
                k++;
            }
            float u0 = __shfl_sync(FULLM, u, 0);
            int ex = (__float_as_int(u0) >> 23) - 127;
            Cl2 += (float)ex;
            if (act) u = __int_as_float(__float_as_int(u) - (ex << 23));
        }
        if (act) g_midu[seq * 32 + lane] = u;       // u_511
        if (lane == 0) g_cbw[seq] = Cl2;
    }
}

// ---------------------------------------------------------------------------
// Kernel 3: per-sequence unnormalized score + combine halves.
//   score: lane handles 32 consecutive m; labels preloaded (int4) so all
//   emission gathers are independent.
// ---------------------------------------------------------------------------
__global__ __launch_bounds__(32) void score_combine(const int* __restrict__ labels,
                                                    const float* __restrict__ Tg) {
    const int seq  = blockIdx.x;
    const int lane = threadIdx.x;
    const float* er = g_e + (size_t)seq * M_ * N_;
    const int*  lab = labels + seq * M_;

    // dot(v_mid, u_mid)
    float pv = (lane < N_) ? g_midv[seq * 32 + lane] * g_midu[seq * 32 + lane] : 0.f;
#pragma unroll
    for (int off = 16; off; off >>= 1) pv += __shfl_xor_sync(FULLM, pv, off);

    // preload this lane's 32 labels
    int y[32];
    {
        const int4* lp = (const int4*)(lab + lane * 32);
#pragma unroll
        for (int i = 0; i < 8; i++) {
            int4 q = __ldg(lp + i);
            y[i * 4] = q.x; y[i * 4 + 1] = q.y; y[i * 4 + 2] = q.z; y[i * 4 + 3] = q.w;
        }
    }
    int y_next0 = __shfl_down_sync(FULLM, y[0], 1);  // first label of lane+1

    float se = 0.f, st = 0.f;
#pragma unroll
    for (int i = 0; i < 32; i++) {
        const int m = lane * 32 + i;
        se += __ldg(er + (size_t)m * 26 + y[i]);
        const int yn = (i < 31) ? y[i + 1] : y_next0;
        if (m < 1023) st += __ldg(Tg + y[i] * 26 + yn);
    }
    float sc = se + st;
#pragma unroll
    for (int off = 16; off; off >>= 1) sc += __shfl_xor_sync(FULLM, sc, off);

    if (lane == 0) {
        const float LN2 = 0.6931471805599453f;
        float logZ = (g_cfw[seq] + g_cbw[seq]) * LN2 + __logf(pv);
        g_res[seq] = sc - logZ;
    }
}

// ---------------------------------------------------------------------------
// Kernel 4: mean over 256 sequences -> d_out[0]
// ---------------------------------------------------------------------------
__global__ __launch_bounds__(256) void reduce_kernel(float* __restrict__ out) {
    const int tid = threadIdx.x;
    float val = g_res[tid];
#pragma unroll
    for (int off = 16; off; off >>= 1) val += __shfl_xor_sync(FULLM, val, off);

    __shared__ float sh[8];
    if ((tid & 31) == 0) sh[tid >> 5] = val;
    __syncthreads();
    if (tid < 8) {
        float t = sh[tid];
#pragma unroll
        for (int off = 4; off; off >>= 1) t += __shfl_xor_sync(0xffu, t, off);
        if (tid == 0) out[0] = t * (1.0f / 256.0f);
    }
}

// ---------------------------------------------------------------------------
extern "C" void kernel_launch(void* const* d_in, const int* in_sizes, int n_in,
                              void* d_out, int out_size) {
    const float* X      = (const float*)d_in[0];   // [256,1024,128] f32
    const int*   labels = (const int*)d_in[1];     // [256,1024] i32
    const float* W      = (const float*)d_in[2];   // [26,128] f32
    const float* Tm     = (const float*)d_in[3];   // [26,26] f32

    emis_kernel<<<1024, 256>>>(X, W);
    scan_kernel<<<2 * B_, 32>>>(Tm);
    score_combine<<<B_, 32>>>(labels, Tm);
    reduce_kernel<<<1, 256>>>((float*)d_out);
}

// round 4
// speedup vs baseline: 4.1214x; 1.8004x over previous
#include <cuda_runtime.h>
#include <cstdint>

// CRF log-likelihood: B=256, M=1024, D=128, N=26.
//   1) emis_kernel     : e = X @ W^T                       (f32x2 FFMA GEMM)
//   2) scan_kernel     : grid 512 — forward half (v) and adjoint half (u)
//                        per sequence, meeting at m=511.  smem-broadcast
//                        matvec (7x LDS.128) instead of 26x SHFL.
//   3) score_combine   : unnormalized score (parallel over m) + dot(v,u)
//   4) reduce_kernel   : mean -> d_out[0]

#define B_ 256
#define M_ 1024
#define D_ 128
#define N_ 26
#define FULLM 0xffffffffu

__device__ float g_e[(size_t)B_ * M_ * N_];   // 27.3 MB emissions
__device__ float g_midv[B_ * 32];             // forward state at m=511
__device__ float g_midu[B_ * 32];             // adjoint state at m=511
__device__ float g_cfw[B_];                   // forward log2-scale
__device__ float g_cbw[B_];                   // backward log2-scale
__device__ float g_res[B_];                   // per-sequence log-probs

__device__ __forceinline__ unsigned long long fma2(unsigned long long a,
                                                   unsigned long long b,
                                                   unsigned long long c) {
    unsigned long long d;
    asm("fma.rn.f32x2 %0, %1, %2, %3;" : "=l"(d) : "l"(a), "l"(b), "l"(c));
    return d;
}

// dot of broadcast state (7 float4 = 28 floats, 26 valid) with per-lane ETc
__device__ __forceinline__ float dot26(const float4 t[7], const float* ETc) {
    float a0 = t[0].x * ETc[0], a1 = t[0].y * ETc[1];
    float a2 = t[0].z * ETc[2], a3 = t[0].w * ETc[3];
#pragma unroll
    for (int q = 1; q < 6; q++) {
        a0 += t[q].x * ETc[q * 4 + 0];
        a1 += t[q].y * ETc[q * 4 + 1];
        a2 += t[q].z * ETc[q * 4 + 2];
        a3 += t[q].w * ETc[q * 4 + 3];
    }
    a0 += t[6].x * ETc[24];
    a1 += t[6].y * ETc[25];
    return (a0 + a1) + (a2 + a3);
}

// ---------------------------------------------------------------------------
// Kernel 1: emissions e = X @ W^T  (unchanged this round; 94us)
// ---------------------------------------------------------------------------
__global__ __launch_bounds__(256) void emis_kernel(const float* __restrict__ X,
                                                   const float* __restrict__ W) {
    __shared__ float Ws[26][132];
    __shared__ float xs[8][8][128];

    const int tid = threadIdx.x;
    for (int i = tid; i < 26 * 128; i += 256) Ws[i >> 7][i & 127] = W[i];
    __syncthreads();

    const int w    = tid >> 5;
    const int lane = tid & 31;
    const int a    = lane < 26 ? lane : 25;
    const ulonglong2* wrow = (const ulonglong2*)&Ws[a][0];

    for (int chunk = 0; chunk < 4; chunk++) {
        const int rowbase = blockIdx.x * 256 + w * 32 + chunk * 8;

        const float4* xsrc = (const float4*)(X + (size_t)rowbase * D_);
        float4* xdst = (float4*)&xs[w][0][0];
#pragma unroll
        for (int i = 0; i < 8; i++) xdst[i * 32 + lane] = xsrc[i * 32 + lane];
        __syncwarp();

        unsigned long long acc[8][2];
#pragma unroll
        for (int r = 0; r < 8; r++) { acc[r][0] = 0ull; acc[r][1] = 0ull; }

#pragma unroll
        for (int d4 = 0; d4 < 32; d4++) {
            const ulonglong2 w2 = wrow[d4];
#pragma unroll
            for (int r = 0; r < 8; r++) {
                const ulonglong2 x2 = *(const ulonglong2*)&xs[w][r][d4 * 4];
                acc[r][0] = fma2(x2.x, w2.x, acc[r][0]);
                acc[r][1] = fma2(x2.y, w2.y, acc[r][1]);
            }
        }

#pragma unroll
        for (int r = 0; r < 8; r++) {
            float lo0 = __int_as_float((int)(acc[r][0] & 0xffffffffull));
            float hi0 = __int_as_float((int)(acc[r][0] >> 32));
            float lo1 = __int_as_float((int)(acc[r][1] & 0xffffffffull));
            float hi1 = __int_as_float((int)(acc[r][1] >> 32));
            float s = (lo0 + hi0) + (lo1 + hi1);
            if (lane < 26) g_e[(size_t)(rowbase + r) * N_ + lane] = s;
        }
        __syncwarp();
    }
}

// ---------------------------------------------------------------------------
// Kernel 2: split scan, smem-broadcast matvec.
//   even block -> forward  v_m[a] = E_m[a] * sum_b exp(T[b,a]) v_{m-1}[b]
//   odd  block -> adjoint  u_{m-1}[b] = sum_a exp(T[b,a]) (E_m[a] u_m[a])
//   State exchanged through double-buffered smem: STS 4B + syncwarp + 7
//   broadcast LDS.128.  Renorm every 8 steps from the already-loaded t[0].x.
// ---------------------------------------------------------------------------
__global__ __launch_bounds__(32) void scan_kernel(const float* __restrict__ Tg) {
    __shared__ __align__(16) float vbuf[2][32];

    const int seq  = blockIdx.x >> 1;
    const int bwd  = blockIdx.x & 1;
    const int lane = threadIdx.x;
    const bool act = lane < N_;
    const float* er = g_e + (size_t)seq * M_ * N_;

    float Cl2 = 0.f;

    if (!bwd) {
        // ---------------- forward: lane = destination label a ----------------
        float ETc[26];                              // ETc[b] = exp(T[b][lane])
#pragma unroll
        for (int b = 0; b < 26; b++)
            ETc[b] = act ? __expf(__ldg(Tg + b * 26 + lane)) : 0.f;

        float v = act ? __expf(__ldg(er + lane)) : 0.f;   // v_0 = exp(e_0)

        float ebuf[8];
#pragma unroll
        for (int i = 0; i < 8; i++)
            ebuf[i] = act ? __ldg(er + (size_t)(1 + i) * 26 + lane) : 0.f;
        float Ecur = __expf(ebuf[0]);

        if (act) vbuf[0][lane] = v;                 // state for m=0
        __syncwarp();

        int m = 1;
        for (int blk = 0; blk < 63; blk++) {        // m = 1..504
#pragma unroll
            for (int j = 0; j < 8; j++) {
                float Enext = __expf(ebuf[(j + 1) & 7]);

                float4 t[7];
                const float4* vp = (const float4*)&vbuf[j & 1][0];
#pragma unroll
                for (int q = 0; q < 7; q++) t[q] = vp[q];

                v = Ecur * dot26(t, ETc);
                Ecur = Enext;

                if (j == 7) {                       // renorm from broadcast pivot
                    int ex = (__float_as_int(t[0].x) >> 23) - 127;
                    Cl2 += (float)ex;
                    if (act) v = __int_as_float(__float_as_int(v) - (ex << 23));
                }

                const int mn = m + 8;               // refill ring
                if (mn <= 511)
                    ebuf[j] = act ? __ldg(er + (size_t)mn * 26 + lane) : 0.f;

                if (act) vbuf[(j + 1) & 1][lane] = v;
                __syncwarp();
                m++;
            }
        }
        // tail m = 505..511 (j = 0..6)
#pragma unroll
        for (int j = 0; j < 7; j++) {
            float Enext = (j < 6) ? __expf(ebuf[j + 1]) : 1.f;
            float4 t[7];
            const float4* vp = (const float4*)&vbuf[j & 1][0];
#pragma unroll
            for (int q = 0; q < 7; q++) t[q] = vp[q];
            v = Ecur * dot26(t, ETc);
            Ecur = Enext;
            if (act) vbuf[(j + 1) & 1][lane] = v;
            __syncwarp();
        }
        if (act) g_midv[seq * 32 + lane] = v;
        if (lane == 0) g_cfw[seq] = Cl2;
    } else {
        // ------------- backward adjoint: lane = source label b ---------------
        float ETr[26];                              // ETr[a] = exp(T[lane][a])
#pragma unroll
        for (int a = 0; a < 26; a++)
            ETr[a] = act ? __expf(__ldg(Tg + lane * 26 + a)) : 0.f;

        float u = act ? 1.f : 0.f;                  // u_1023 = 1

        float ebuf[8];
#pragma unroll
        for (int i = 0; i < 8; i++)
            ebuf[i] = act ? __ldg(er + (size_t)(1023 - i) * 26 + lane) : 0.f;
        float Ecur = __expf(ebuf[0]);               // E_1023

        // store s_1023 = E_1023 * u_1023
        if (act) vbuf[0][lane] = Ecur * u;
        __syncwarp();

        int k = 0;
        for (int blk = 0; blk < 64; blk++) {        // k = 0..511
#pragma unroll
            for (int j = 0; j < 8; j++) {
                float Enext = __expf(ebuf[(j + 1) & 7]);

                float4 t[7];
                const float4* vp = (const float4*)&vbuf[j & 1][0];
#pragma unroll
                for (int q = 0; q < 7; q++) t[q] = vp[q];

                u = dot26(t, ETr);                  // u at level m-1
                Ecur = Enext;

                if (j == 7) {
                    int ex = (__float_as_int(t[0].x) >> 23) - 127;
                    Cl2 += (float)ex;
                    if (act) u = __int_as_float(__float_as_int(u) - (ex << 23));
                }

                const int kn = k + 8;               // refill ring
                if (kn <= 511)
                    ebuf[j] = act ? __ldg(er + (size_t)(1023 - kn) * 26 + lane) : 0.f;

                // store s = E_{m-1} * u_{m-1} for the next step (skip on last)
                if (act) vbuf[(j + 1) & 1][lane] = Ecur * u;
                __syncwarp();
                k++;
            }
        }
        if (act) g_midu[seq * 32 + lane] = u;       // u_511
        if (lane == 0) g_cbw[seq] = Cl2;
    }
}

// ---------------------------------------------------------------------------
// Kernel 3: per-sequence unnormalized score + combine halves.
// ---------------------------------------------------------------------------
__global__ __launch_bounds__(32) void score_combine(const int* __restrict__ labels,
                                                    const float* __restrict__ Tg) {
    const int seq  = blockIdx.x;
    const int lane = threadIdx.x;
    const float* er = g_e + (size_t)seq * M_ * N_;
    const int*  lab = labels + seq * M_;

    float pv = (lane < N_) ? g_midv[seq * 32 + lane] * g_midu[seq * 32 + lane] : 0.f;
#pragma unroll
    for (int off = 16; off; off >>= 1) pv += __shfl_xor_sync(FULLM, pv, off);

    int y[32];
    {
        const int4* lp = (const int4*)(lab + lane * 32);
#pragma unroll
        for (int i = 0; i < 8; i++) {
            int4 q = __ldg(lp + i);
            y[i * 4] = q.x; y[i * 4 + 1] = q.y; y[i * 4 + 2] = q.z; y[i * 4 + 3] = q.w;
        }
    }
    int y_next0 = __shfl_down_sync(FULLM, y[0], 1);

    float se = 0.f, st = 0.f;
#pragma unroll
    for (int i = 0; i < 32; i++) {
        const int m = lane * 32 + i;
        se += __ldg(er + (size_t)m * 26 + y[i]);
        const int yn = (i < 31) ? y[i + 1] : y_next0;
        if (m < 1023) st += __ldg(Tg + y[i] * 26 + yn);
    }
    float sc = se + st;
#pragma unroll
    for (int off = 16; off; off >>= 1) sc += __shfl_xor_sync(FULLM, sc, off);

    if (lane == 0) {
        const float LN2 = 0.6931471805599453f;
        float logZ = (g_cfw[seq] + g_cbw[seq]) * LN2 + __logf(pv);
        g_res[seq] = sc - logZ;
    }
}

// ---------------------------------------------------------------------------
// Kernel 4: mean over 256 sequences -> d_out[0]
// ---------------------------------------------------------------------------
__global__ __launch_bounds__(256) void reduce_kernel(float* __restrict__ out) {
    const int tid = threadIdx.x;
    float val = g_res[tid];
#pragma unroll
    for (int off = 16; off; off >>= 1) val += __shfl_xor_sync(FULLM, val, off);

    __shared__ float sh[8];
    if ((tid & 31) == 0) sh[tid >> 5] = val;
    __syncthreads();
    if (tid < 8) {
        float t = sh[tid];
#pragma unroll
        for (int off = 4; off; off >>= 1) t += __shfl_xor_sync(0xffu, t, off);
        if (tid == 0) out[0] = t * (1.0f / 256.0f);
    }
}

// ---------------------------------------------------------------------------
extern "C" void kernel_launch(void* const* d_in, const int* in_sizes, int n_in,
                              void* d_out, int out_size) {
    const float* X      = (const float*)d_in[0];   // [256,1024,128] f32
    const int*   labels = (const int*)d_in[1];     // [256,1024] i32
    const float* W      = (const float*)d_in[2];   // [26,128] f32
    const float* Tm     = (const float*)d_in[3];   // [26,26] f32

    emis_kernel<<<1024, 256>>>(X, W);
    scan_kernel<<<2 * B_, 32>>>(Tm);
    score_combine<<<B_, 32>>>(labels, Tm);
    reduce_kernel<<<1, 256>>>((float*)d_out);
}